// round 2
// baseline (speedup 1.0000x reference)
#include <cuda_runtime.h>
#include <cuda_bf16.h>

#define NN 50000
#define NE 800000
#define NET (NN + NE)

// ---------------- scratch (static device globals; no allocation) -------------
__device__ float g_h1[NN * 256];      // layer1 pre-attention features [N,8,32]
__device__ float g_asrc1[NN * 8];
__device__ float g_adst1[NN * 8];
__device__ float g_hin2[NN * 256];    // elu(layer1 out) = layer2 input
__device__ float g_h2[NN * 64];       // layer2 pre-attention features
__device__ float g_asrc2[NN];
__device__ float g_adst2[NN];
__device__ float g_expw1[NET * 8];    // exp(e) per (csr-pos, head), layer1
__device__ float g_ssum1[NN * 8];
__device__ float g_expw2[NET];
__device__ float g_ssum2[NN];
__device__ int   g_deg[NN];
__device__ int   g_rowptr[NN + 1];
__device__ int   g_pos[NN];
__device__ int   g_ssrc[NET];         // CSR-ordered source node ids
__device__ int   g_sdst[NET];         // CSR-ordered dest node ids
__device__ int   g_is64;              // 1 if edge_index is int64, 0 if int32

// ---------------- edge_index dtype detection ---------------------------------
// int64 node ids < 50000 have zero high words; int32 data has random ids there.
__global__ void k_detect(const int* __restrict__ w) {
    if (threadIdx.x == 0) {
        int all0 = 1;
        for (int i = 1; i < 200; i += 2)
            if (w[i] != 0) { all0 = 0; break; }
        g_is64 = all0;
    }
}

__device__ __forceinline__ int load_idx(const void* ei, long long pos, int is64) {
    if (is64) return (int)((const long long*)ei)[pos];
    return ((const int*)ei)[pos];
}

// ---------------- zero counters ----------------------------------------------
__global__ void k_zero(int n) {
    int i = blockIdx.x * blockDim.x + threadIdx.x;
    if (i < n) { g_deg[i] = 0; g_ssum2[i] = 0.f; }
    if (i < n * 8) g_ssum1[i] = 0.f;
}

// ---------------- generic fp32 tiled GEMM: C[M,Nc] = A[M,K] @ B[K,Nc] --------
// BM=BN=64, BK=16, 256 threads, 4x4 register tile.
__global__ void __launch_bounds__(256) k_gemm(
    const float* __restrict__ A, const float* __restrict__ B,
    float* __restrict__ C, int M, int Nc, int K)
{
    __shared__ float As[16][68];   // [k][m], pad keeps float4 alignment
    __shared__ float Bs[16][64];   // [k][n]
    const int t  = threadIdx.x;
    const int tx = t & 15, ty = t >> 4;
    const int n0 = blockIdx.x * 64, m0 = blockIdx.y * 64;

    float acc[16];
#pragma unroll
    for (int i = 0; i < 16; i++) acc[i] = 0.f;

    for (int k0 = 0; k0 < K; k0 += 16) {
        __syncthreads();
#pragma unroll
        for (int l = 0; l < 4; l++) {
            int idx = t + l * 256;
            int r = idx >> 4, kk = idx & 15;
            int m = m0 + r;
            As[kk][r] = (m < M) ? A[m * K + k0 + kk] : 0.f;
        }
#pragma unroll
        for (int l = 0; l < 4; l++) {
            int idx = t + l * 256;
            int kk = idx >> 6, nn = idx & 63;
            Bs[kk][nn] = B[(k0 + kk) * Nc + n0 + nn];
        }
        __syncthreads();
#pragma unroll
        for (int k = 0; k < 16; k++) {
            float4 a = *(const float4*)&As[k][ty * 4];
            float4 b = *(const float4*)&Bs[k][tx * 4];
            acc[0]  += a.x * b.x; acc[1]  += a.x * b.y; acc[2]  += a.x * b.z; acc[3]  += a.x * b.w;
            acc[4]  += a.y * b.x; acc[5]  += a.y * b.y; acc[6]  += a.y * b.z; acc[7]  += a.y * b.w;
            acc[8]  += a.z * b.x; acc[9]  += a.z * b.y; acc[10] += a.z * b.z; acc[11] += a.z * b.w;
            acc[12] += a.w * b.x; acc[13] += a.w * b.y; acc[14] += a.w * b.z; acc[15] += a.w * b.w;
        }
    }
#pragma unroll
    for (int i = 0; i < 4; i++) {
        int m = m0 + ty * 4 + i;
        if (m < M) {
#pragma unroll
            for (int j = 0; j < 4; j++)
                C[m * Nc + n0 + tx * 4 + j] = acc[i * 4 + j];
        }
    }
}

// ---------------- layer1 attention logits per node ----------------------------
__global__ void k_att1(const float* __restrict__ att_src,
                       const float* __restrict__ att_dst, int n)
{
    int i = blockIdx.x * blockDim.x + threadIdx.x;  // over n*8
    if (i >= n * 8) return;
    int node = i >> 3, h = i & 7;
    const float* hp = &g_h1[node * 256 + h * 32];
    float sa = 0.f, sd = 0.f;
#pragma unroll
    for (int c = 0; c < 32; c++) {
        float v = hp[c];
        sa += v * att_src[h * 32 + c];
        sd += v * att_dst[h * 32 + c];
    }
    g_asrc1[i] = sa; g_adst1[i] = sd;
}

// ---------------- CSR build ---------------------------------------------------
__global__ void k_count(const void* __restrict__ ei, int e, int n) {
    int i = blockIdx.x * blockDim.x + threadIdx.x;
    if (i >= e + n) return;
    int is64 = g_is64;
    int d = (i < e) ? load_idx(ei, (long long)e + i, is64) : (i - e);
    atomicAdd(&g_deg[d], 1);
}

__global__ void __launch_bounds__(1024) k_scan(int n) {
    const int CH = 49;  // 1024*49 >= 50000
    int t = threadIdx.x;
    int base = t * CH;
    int s = 0;
    for (int i = 0; i < CH; i++) { int idx = base + i; if (idx < n) s += g_deg[idx]; }
    int lane = t & 31, wid = t >> 5;
    int v = s;
#pragma unroll
    for (int o = 1; o < 32; o <<= 1) {
        int u = __shfl_up_sync(0xffffffffu, v, o);
        if (lane >= o) v += u;
    }
    __shared__ int ws[32];
    if (lane == 31) ws[wid] = v;
    __syncthreads();
    if (wid == 0) {
        int w = ws[lane];
#pragma unroll
        for (int o = 1; o < 32; o <<= 1) {
            int u = __shfl_up_sync(0xffffffffu, w, o);
            if (lane >= o) w += u;
        }
        ws[lane] = w;
    }
    __syncthreads();
    int excl = v - s + (wid > 0 ? ws[wid - 1] : 0);
    int run = excl;
    for (int i = 0; i < CH; i++) {
        int idx = base + i;
        if (idx < n) { g_rowptr[idx] = run; g_pos[idx] = run; run += g_deg[idx]; }
    }
    if (t == 1023) g_rowptr[n] = excl;  // t=1023's chunk lies past n -> excl == total
}

__global__ void k_scatter(const void* __restrict__ ei, int e, int n) {
    int i = blockIdx.x * blockDim.x + threadIdx.x;
    if (i >= e + n) return;
    int is64 = g_is64;
    int s, d;
    if (i < e) { s = load_idx(ei, i, is64); d = load_idx(ei, (long long)e + i, is64); }
    else       { s = i - e;                 d = i - e; }
    int p = atomicAdd(&g_pos[d], 1);
    g_ssrc[p] = s;
    g_sdst[p] = d;
}

// ---------------- layer1 softmax numerators + denominators --------------------
__global__ void k_exp1(int et) {
    int i = blockIdx.x * blockDim.x + threadIdx.x;  // over et*8
    if (i >= et * 8) return;
    int p = i >> 3, h = i & 7;
    int s = g_ssrc[p], d = g_sdst[p];
    float ev = g_asrc1[s * 8 + h] + g_adst1[d * 8 + h];
    ev = ev > 0.f ? ev : 0.2f * ev;              // leaky relu
    float ex = __expf(ev);                       // no max-shift needed: |ev| small
    g_expw1[i] = ex;
    atomicAdd(&g_ssum1[d * 8 + h], ex);
}

// ---------------- layer1 aggregation + bias + ELU -----------------------------
__global__ void __launch_bounds__(256) k_agg1(const float* __restrict__ bias1) {
    int d = blockIdx.x;
    int t = threadIdx.x;           // t = h*32 + c
    int h = t >> 5;
    int r0 = g_rowptr[d], r1 = g_rowptr[d + 1];
    float sinv = 1.f / (g_ssum1[d * 8 + h] + 1e-16f);
    float acc = 0.f;
    for (int p = r0; p < r1; p++) {
        int s = g_ssrc[p];
        float w = g_expw1[p * 8 + h];
        acc += w * g_h1[s * 256 + t];
    }
    float v = acc * sinv + bias1[t];
    g_hin2[d * 256 + t] = v > 0.f ? v : expm1f(v);   // elu
}

// ---------------- layer2 attention logits (warp per node) ---------------------
__global__ void k_att2(const float* __restrict__ as2,
                       const float* __restrict__ ad2, int n)
{
    int w = (blockIdx.x * blockDim.x + threadIdx.x) >> 5;
    int lane = threadIdx.x & 31;
    if (w >= n) return;
    float v0 = g_h2[w * 64 + lane], v1 = g_h2[w * 64 + 32 + lane];
    float sa = v0 * as2[lane] + v1 * as2[32 + lane];
    float sd = v0 * ad2[lane] + v1 * ad2[32 + lane];
#pragma unroll
    for (int o = 16; o; o >>= 1) {
        sa += __shfl_xor_sync(0xffffffffu, sa, o);
        sd += __shfl_xor_sync(0xffffffffu, sd, o);
    }
    if (lane == 0) { g_asrc2[w] = sa; g_adst2[w] = sd; }
}

__global__ void k_exp2(int et) {
    int p = blockIdx.x * blockDim.x + threadIdx.x;
    if (p >= et) return;
    int s = g_ssrc[p], d = g_sdst[p];
    float ev = g_asrc2[s] + g_adst2[d];
    ev = ev > 0.f ? ev : 0.2f * ev;
    float ex = __expf(ev);
    g_expw2[p] = ex;
    atomicAdd(&g_ssum2[d], ex);
}

// ---------------- layer2 aggregation + bias -> output -------------------------
__global__ void __launch_bounds__(64) k_agg2(const float* __restrict__ bias2,
                                             float* __restrict__ out)
{
    int d = blockIdx.x;
    int c = threadIdx.x;           // 64 threads
    int r0 = g_rowptr[d], r1 = g_rowptr[d + 1];
    float sinv = 1.f / (g_ssum2[d] + 1e-16f);
    float acc = 0.f;
    for (int p = r0; p < r1; p++) {
        int s = g_ssrc[p];
        acc += g_expw2[p] * g_h2[s * 64 + c];
    }
    out[d * 64 + c] = acc * sinv + bias2[c];
}

// ------------------------------------------------------------------------------
extern "C" void kernel_launch(void* const* d_in, const int* in_sizes, int n_in,
                              void* d_out, int out_size)
{
    const float* x   = (const float*)d_in[0];
    const void*  ei  = d_in[1];           // int32 or int64, detected on device
    // d_in[2] edge_weight: unused (edge_dim=None in reference)
    const float* W1  = (const float*)d_in[3];
    const float* as1 = (const float*)d_in[4];
    const float* ad1 = (const float*)d_in[5];
    const float* b1  = (const float*)d_in[6];
    const float* W2  = (const float*)d_in[7];
    const float* as2 = (const float*)d_in[8];
    const float* ad2 = (const float*)d_in[9];
    const float* b2  = (const float*)d_in[10];
    float* out = (float*)d_out;

    const int n  = in_sizes[0] / 128;   // 50000
    const int e  = in_sizes[1] / 2;     // 800000
    const int et = e + n;

    float *h1, *hin2, *h2;
    cudaGetSymbolAddress((void**)&h1,   g_h1);
    cudaGetSymbolAddress((void**)&hin2, g_hin2);
    cudaGetSymbolAddress((void**)&h2,   g_h2);

    // dtype detection + zero counters
    k_detect<<<1, 32>>>((const int*)ei);
    k_zero<<<(n * 8 + 255) / 256, 256>>>(n);

    // layer1 GEMM: h1 = x @ W1
    k_gemm<<<dim3(256 / 64, (n + 63) / 64), 256>>>(x, W1, h1, n, 256, 128);

    // per-node attention logits
    k_att1<<<(n * 8 + 255) / 256, 256>>>(as1, ad1, n);

    // CSR build (shared by both layers)
    k_count<<<(et + 255) / 256, 256>>>(ei, e, n);
    k_scan<<<1, 1024>>>(n);
    k_scatter<<<(et + 255) / 256, 256>>>(ei, e, n);

    // layer1 softmax + aggregation (+bias +elu)
    k_exp1<<<(et * 8 + 255) / 256, 256>>>(et);
    k_agg1<<<n, 256>>>(b1);

    // layer2 GEMM: h2 = elu_out @ W2
    k_gemm<<<dim3(1, (n + 63) / 64), 256>>>(hin2, W2, h2, n, 64, 256);

    // layer2 logits, softmax, aggregation (+bias) -> output
    k_att2<<<(n * 32 + 255) / 256, 256>>>(as2, ad2, n);
    k_exp2<<<(et + 255) / 256, 256>>>(et);
    k_agg2<<<n, 64>>>(b2, out);
}

// round 4
// speedup vs baseline: 2.0152x; 2.0152x over previous
#include <cuda_runtime.h>
#include <cuda_bf16.h>

#define NN 50000
#define NE 800000
#define NET (NN + NE)

// ---------------- scratch (static device globals; no allocation) -------------
__device__ float g_h1[NN * 256];      // layer1 pre-attention features [N,8,32]
__device__ float g_asrc1[NN * 8];
__device__ float g_adst1[NN * 8];
__device__ float g_hin2[NN * 256];    // elu(layer1 out) = layer2 input
__device__ float g_h2[NN * 64];       // layer2 pre-attention features
__device__ float g_asrc2[NN];
__device__ float g_adst2[NN];
__device__ float g_expw1[NET * 8];    // exp(e) per (csr-pos, head), layer1
__device__ float g_expw2[NET];
__device__ int   g_deg[NN];
__device__ int   g_rowptr[NN + 1];
__device__ int   g_pos[NN];
__device__ int   g_ssrc[NET];         // CSR-ordered source node ids
__device__ int   g_sdst[NET];         // CSR-ordered dest node ids
__device__ int   g_is64;              // 1 if edge_index is int64, 0 if int32

// ---------------- edge_index dtype detection ---------------------------------
__global__ void k_detect(const int* __restrict__ w) {
    if (threadIdx.x == 0) {
        int all0 = 1;
        for (int i = 1; i < 200; i += 2)
            if (w[i] != 0) { all0 = 0; break; }
        g_is64 = all0;
    }
}

__device__ __forceinline__ int load_idx(const void* ei, long long pos, int is64) {
    if (is64) return (int)((const long long*)ei)[pos];
    return ((const int*)ei)[pos];
}

// ---------------- zero counters ----------------------------------------------
__global__ void k_zero(int n) {
    int i = blockIdx.x * blockDim.x + threadIdx.x;
    if (i < n) g_deg[i] = 0;
}

// ---------------- generic fp32 tiled GEMM: C[M,Nc] = A[M,K] @ B[K,Nc] --------
__global__ void __launch_bounds__(256) k_gemm(
    const float* __restrict__ A, const float* __restrict__ B,
    float* __restrict__ C, int M, int Nc, int K)
{
    __shared__ float As[16][68];
    __shared__ float Bs[16][64];
    const int t  = threadIdx.x;
    const int tx = t & 15, ty = t >> 4;
    const int n0 = blockIdx.x * 64, m0 = blockIdx.y * 64;

    float acc[16];
#pragma unroll
    for (int i = 0; i < 16; i++) acc[i] = 0.f;

    for (int k0 = 0; k0 < K; k0 += 16) {
        __syncthreads();
#pragma unroll
        for (int l = 0; l < 4; l++) {
            int idx = t + l * 256;
            int r = idx >> 4, kk = idx & 15;
            int m = m0 + r;
            As[kk][r] = (m < M) ? A[m * K + k0 + kk] : 0.f;
        }
#pragma unroll
        for (int l = 0; l < 4; l++) {
            int idx = t + l * 256;
            int kk = idx >> 6, nn = idx & 63;
            Bs[kk][nn] = B[(k0 + kk) * Nc + n0 + nn];
        }
        __syncthreads();
#pragma unroll
        for (int k = 0; k < 16; k++) {
            float4 a = *(const float4*)&As[k][ty * 4];
            float4 b = *(const float4*)&Bs[k][tx * 4];
            acc[0]  += a.x * b.x; acc[1]  += a.x * b.y; acc[2]  += a.x * b.z; acc[3]  += a.x * b.w;
            acc[4]  += a.y * b.x; acc[5]  += a.y * b.y; acc[6]  += a.y * b.z; acc[7]  += a.y * b.w;
            acc[8]  += a.z * b.x; acc[9]  += a.z * b.y; acc[10] += a.z * b.z; acc[11] += a.z * b.w;
            acc[12] += a.w * b.x; acc[13] += a.w * b.y; acc[14] += a.w * b.z; acc[15] += a.w * b.w;
        }
    }
#pragma unroll
    for (int i = 0; i < 4; i++) {
        int m = m0 + ty * 4 + i;
        if (m < M) {
#pragma unroll
            for (int j = 0; j < 4; j++)
                C[m * Nc + n0 + tx * 4 + j] = acc[i * 4 + j];
        }
    }
}

// ---------------- layer1 attention logits: warp per node ----------------------
__global__ void __launch_bounds__(256) k_att1(const float* __restrict__ att_src,
                                              const float* __restrict__ att_dst, int n)
{
    int warp = (blockIdx.x * blockDim.x + threadIdx.x) >> 5;
    int lane = threadIdx.x & 31;
    if (warp >= n) return;
    float wsrc[8], wdst[8];
#pragma unroll
    for (int h = 0; h < 8; h++) {
        wsrc[h] = att_src[h * 32 + lane];
        wdst[h] = att_dst[h * 32 + lane];
    }
    const float* hp = &g_h1[warp * 256];
    float sa = 0.f, sd = 0.f;
#pragma unroll
    for (int h = 0; h < 8; h++) {
        float v = hp[h * 32 + lane];          // coalesced: one 128B line
        float p1 = v * wsrc[h];
        float p2 = v * wdst[h];
#pragma unroll
        for (int o = 16; o; o >>= 1) {
            p1 += __shfl_xor_sync(0xffffffffu, p1, o);
            p2 += __shfl_xor_sync(0xffffffffu, p2, o);
        }
        if (lane == h) { sa = p1; sd = p2; }
    }
    if (lane < 8) {
        g_asrc1[warp * 8 + lane] = sa;
        g_adst1[warp * 8 + lane] = sd;
    }
}

// ---------------- CSR build ---------------------------------------------------
__global__ void k_count(const void* __restrict__ ei, int e, int n) {
    int i = blockIdx.x * blockDim.x + threadIdx.x;
    if (i >= e + n) return;
    int is64 = g_is64;
    int d = (i < e) ? load_idx(ei, (long long)e + i, is64) : (i - e);
    atomicAdd(&g_deg[d], 1);
}

__global__ void __launch_bounds__(1024) k_scan(int n) {
    const int CH = 49;
    int t = threadIdx.x;
    int base = t * CH;
    int s = 0;
    for (int i = 0; i < CH; i++) { int idx = base + i; if (idx < n) s += g_deg[idx]; }
    int lane = t & 31, wid = t >> 5;
    int v = s;
#pragma unroll
    for (int o = 1; o < 32; o <<= 1) {
        int u = __shfl_up_sync(0xffffffffu, v, o);
        if (lane >= o) v += u;
    }
    __shared__ int ws[32];
    if (lane == 31) ws[wid] = v;
    __syncthreads();
    if (wid == 0) {
        int w = ws[lane];
#pragma unroll
        for (int o = 1; o < 32; o <<= 1) {
            int u = __shfl_up_sync(0xffffffffu, w, o);
            if (lane >= o) w += u;
        }
        ws[lane] = w;
    }
    __syncthreads();
    int excl = v - s + (wid > 0 ? ws[wid - 1] : 0);
    int run = excl;
    for (int i = 0; i < CH; i++) {
        int idx = base + i;
        if (idx < n) { g_rowptr[idx] = run; g_pos[idx] = run; run += g_deg[idx]; }
    }
    if (t == 1023) g_rowptr[n] = excl;
}

__global__ void k_scatter(const void* __restrict__ ei, int e, int n) {
    int i = blockIdx.x * blockDim.x + threadIdx.x;
    if (i >= e + n) return;
    int is64 = g_is64;
    int s, d;
    if (i < e) { s = load_idx(ei, i, is64); d = load_idx(ei, (long long)e + i, is64); }
    else       { s = i - e;                 d = i - e; }
    int p = atomicAdd(&g_pos[d], 1);
    g_ssrc[p] = s;
    g_sdst[p] = d;
}

// ---------------- layer1 softmax numerators (stream, no atomics) --------------
__global__ void k_exp1(int et) {
    int p = blockIdx.x * blockDim.x + threadIdx.x;
    if (p >= et) return;
    int s = g_ssrc[p], d = g_sdst[p];
    const float4* AS = (const float4*)g_asrc1;
    const float4* AD = (const float4*)g_adst1;
    float4 a0 = AS[s * 2], a1 = AS[s * 2 + 1];
    float4 d0 = AD[d * 2], d1 = AD[d * 2 + 1];
    float4 r0, r1;
    float e0;
    e0 = a0.x + d0.x; e0 = e0 > 0.f ? e0 : 0.2f * e0; r0.x = __expf(e0);
    e0 = a0.y + d0.y; e0 = e0 > 0.f ? e0 : 0.2f * e0; r0.y = __expf(e0);
    e0 = a0.z + d0.z; e0 = e0 > 0.f ? e0 : 0.2f * e0; r0.z = __expf(e0);
    e0 = a0.w + d0.w; e0 = e0 > 0.f ? e0 : 0.2f * e0; r0.w = __expf(e0);
    e0 = a1.x + d1.x; e0 = e0 > 0.f ? e0 : 0.2f * e0; r1.x = __expf(e0);
    e0 = a1.y + d1.y; e0 = e0 > 0.f ? e0 : 0.2f * e0; r1.y = __expf(e0);
    e0 = a1.z + d1.z; e0 = e0 > 0.f ? e0 : 0.2f * e0; r1.z = __expf(e0);
    e0 = a1.w + d1.w; e0 = e0 > 0.f ? e0 : 0.2f * e0; r1.w = __expf(e0);
    float4* EX = (float4*)g_expw1;
    EX[p * 2] = r0; EX[p * 2 + 1] = r1;
}

// ---------------- layer1 aggregation + softmax-div + bias + ELU ---------------
// 4 nodes per 256-thread block; 64 threads per node; float4 per thread.
__global__ void __launch_bounds__(256) k_agg1(const float* __restrict__ bias1) {
    int t = threadIdx.x;
    int u = t & 63;
    int d = blockIdx.x * 4 + (t >> 6);
    int h = u >> 3;
    int r0 = g_rowptr[d], r1 = g_rowptr[d + 1];
    const float4* H = (const float4*)g_h1;
    float4 acc = make_float4(0.f, 0.f, 0.f, 0.f);
    float wsum = 0.f;
    int p = r0;
    for (; p + 2 <= r1; p += 2) {
        int s0 = g_ssrc[p],     s1 = g_ssrc[p + 1];
        float w0 = g_expw1[p * 8 + h], w1 = g_expw1[(p + 1) * 8 + h];
        float4 v0 = H[s0 * 64 + u];
        float4 v1 = H[s1 * 64 + u];
        acc.x += w0 * v0.x + w1 * v1.x;
        acc.y += w0 * v0.y + w1 * v1.y;
        acc.z += w0 * v0.z + w1 * v1.z;
        acc.w += w0 * v0.w + w1 * v1.w;
        wsum += w0 + w1;
    }
    if (p < r1) {
        int s0 = g_ssrc[p];
        float w0 = g_expw1[p * 8 + h];
        float4 v0 = H[s0 * 64 + u];
        acc.x += w0 * v0.x; acc.y += w0 * v0.y;
        acc.z += w0 * v0.z; acc.w += w0 * v0.w;
        wsum += w0;
    }
    float sinv = 1.f / (wsum + 1e-16f);
    float4 b = ((const float4*)bias1)[u];
    float4 o;
    o.x = acc.x * sinv + b.x; o.x = o.x > 0.f ? o.x : expm1f(o.x);
    o.y = acc.y * sinv + b.y; o.y = o.y > 0.f ? o.y : expm1f(o.y);
    o.z = acc.z * sinv + b.z; o.z = o.z > 0.f ? o.z : expm1f(o.z);
    o.w = acc.w * sinv + b.w; o.w = o.w > 0.f ? o.w : expm1f(o.w);
    ((float4*)g_hin2)[d * 64 + u] = o;
}

// ---------------- layer2 attention logits (warp per node) ---------------------
__global__ void k_att2(const float* __restrict__ as2,
                       const float* __restrict__ ad2, int n)
{
    int w = (blockIdx.x * blockDim.x + threadIdx.x) >> 5;
    int lane = threadIdx.x & 31;
    if (w >= n) return;
    float v0 = g_h2[w * 64 + lane], v1 = g_h2[w * 64 + 32 + lane];
    float sa = v0 * as2[lane] + v1 * as2[32 + lane];
    float sd = v0 * ad2[lane] + v1 * ad2[32 + lane];
#pragma unroll
    for (int o = 16; o; o >>= 1) {
        sa += __shfl_xor_sync(0xffffffffu, sa, o);
        sd += __shfl_xor_sync(0xffffffffu, sd, o);
    }
    if (lane == 0) { g_asrc2[w] = sa; g_adst2[w] = sd; }
}

__global__ void k_exp2(int et) {
    int p = blockIdx.x * blockDim.x + threadIdx.x;
    if (p >= et) return;
    int s = g_ssrc[p], d = g_sdst[p];
    float ev = g_asrc2[s] + g_adst2[d];
    ev = ev > 0.f ? ev : 0.2f * ev;
    g_expw2[p] = __expf(ev);
}

// ---------------- layer2 aggregation + softmax-div + bias -> output -----------
// 16 nodes per 256-thread block; 16 threads per node; float4 per thread.
__global__ void __launch_bounds__(256) k_agg2(const float* __restrict__ bias2,
                                              float* __restrict__ out)
{
    int t = threadIdx.x;
    int u = t & 15;
    int d = blockIdx.x * 16 + (t >> 4);
    int r0 = g_rowptr[d], r1 = g_rowptr[d + 1];
    const float4* H = (const float4*)g_h2;
    float4 acc = make_float4(0.f, 0.f, 0.f, 0.f);
    float wsum = 0.f;
    int p = r0;
    for (; p + 2 <= r1; p += 2) {
        int s0 = g_ssrc[p], s1 = g_ssrc[p + 1];
        float w0 = g_expw2[p], w1 = g_expw2[p + 1];
        float4 v0 = H[s0 * 16 + u];
        float4 v1 = H[s1 * 16 + u];
        acc.x += w0 * v0.x + w1 * v1.x;
        acc.y += w0 * v0.y + w1 * v1.y;
        acc.z += w0 * v0.z + w1 * v1.z;
        acc.w += w0 * v0.w + w1 * v1.w;
        wsum += w0 + w1;
    }
    if (p < r1) {
        int s0 = g_ssrc[p];
        float w0 = g_expw2[p];
        float4 v0 = H[s0 * 16 + u];
        acc.x += w0 * v0.x; acc.y += w0 * v0.y;
        acc.z += w0 * v0.z; acc.w += w0 * v0.w;
        wsum += w0;
    }
    float sinv = 1.f / (wsum + 1e-16f);
    float4 b = ((const float4*)bias2)[u];
    float4 o;
    o.x = acc.x * sinv + b.x;
    o.y = acc.y * sinv + b.y;
    o.z = acc.z * sinv + b.z;
    o.w = acc.w * sinv + b.w;
    ((float4*)out)[d * 16 + u] = o;
}

// ------------------------------------------------------------------------------
extern "C" void kernel_launch(void* const* d_in, const int* in_sizes, int n_in,
                              void* d_out, int out_size)
{
    const float* x   = (const float*)d_in[0];
    const void*  ei  = d_in[1];
    const float* W1  = (const float*)d_in[3];
    const float* as1 = (const float*)d_in[4];
    const float* ad1 = (const float*)d_in[5];
    const float* b1  = (const float*)d_in[6];
    const float* W2  = (const float*)d_in[7];
    const float* as2 = (const float*)d_in[8];
    const float* ad2 = (const float*)d_in[9];
    const float* b2  = (const float*)d_in[10];
    float* out = (float*)d_out;

    const int n  = in_sizes[0] / 128;   // 50000
    const int e  = in_sizes[1] / 2;     // 800000
    const int et = e + n;

    float *h1, *hin2, *h2;
    cudaGetSymbolAddress((void**)&h1,   g_h1);
    cudaGetSymbolAddress((void**)&hin2, g_hin2);
    cudaGetSymbolAddress((void**)&h2,   g_h2);

    k_detect<<<1, 32>>>((const int*)ei);
    k_zero<<<(n + 255) / 256, 256>>>(n);

    // layer1 GEMM: h1 = x @ W1
    k_gemm<<<dim3(256 / 64, (n + 63) / 64), 256>>>(x, W1, h1, n, 256, 128);

    // per-node attention logits (warp per node)
    k_att1<<<(n * 32 + 255) / 256, 256>>>(as1, ad1, n);

    // CSR build (shared by both layers)
    k_count<<<(et + 255) / 256, 256>>>(ei, e, n);
    k_scan<<<1, 1024>>>(n);
    k_scatter<<<(et + 255) / 256, 256>>>(ei, e, n);

    // layer1 softmax numerators + aggregation (+bias +elu)
    k_exp1<<<(et + 255) / 256, 256>>>(et);
    k_agg1<<<(n + 3) / 4, 256>>>(b1);

    // layer2 GEMM: h2 = elu_out @ W2
    k_gemm<<<dim3(1, (n + 63) / 64), 256>>>(hin2, W2, h2, n, 64, 256);

    // layer2 logits, softmax, aggregation (+bias) -> output
    k_att2<<<(n * 32 + 255) / 256, 256>>>(as2, ad2, n);
    k_exp2<<<(et + 255) / 256, 256>>>(et);
    k_agg2<<<(n + 15) / 16, 256>>>(b2, out);
}

// round 5
// speedup vs baseline: 2.0356x; 1.0101x over previous
#include <cuda_runtime.h>
#include <cuda_bf16.h>
#include <cstdint>

#define NN 50000
#define NE 800000
#define NET (NN + NE)

// ---------------- scratch (static device globals; no allocation) -------------
__device__ float g_h1[NN * 256];      // layer1 pre-attention features [N,8,32]
__device__ float g_asrc1[NN * 8];
__device__ float g_adst1[NN * 8];
__device__ float g_h2[NN * 64];       // layer2 pre-attention features
__device__ float g_asrc2[NN];
__device__ float g_adst2[NN];
__device__ float g_expw1[NET * 8];
__device__ float g_expw2[NET];
__device__ int   g_deg[NN];
__device__ int   g_rowptr[NN + 1];
__device__ int   g_pos[NN];
__device__ int   g_ssrc[NET];
__device__ int   g_sdst[NET];
__device__ int   g_is64;

// bf16 split operands (stored as raw ushort bit patterns)
__device__ unsigned short g_xhi[NN * 128];
__device__ unsigned short g_xlo[NN * 128];
__device__ unsigned short g_b1cat[384 * 256];   // vstack(W1_hi, W1_hi, W1_lo)
__device__ unsigned short g_h2hi[NN * 256];     // elu(layer1) hi
__device__ unsigned short g_h2lo[NN * 256];     // elu(layer1) lo
__device__ unsigned short g_b2cat[768 * 64];    // vstack(W2_hi, W2_hi, W2_lo)

__device__ __forceinline__ unsigned short f2bf(float x) {
    __nv_bfloat16 b = __float2bfloat16_rn(x);
    return *(unsigned short*)&b;
}
__device__ __forceinline__ float bf2f(unsigned short u) {
    __nv_bfloat16 b = *(__nv_bfloat16*)&u;
    return __bfloat162float(b);
}

// ---------------- edge_index dtype detection ---------------------------------
__global__ void k_detect(const int* __restrict__ w) {
    if (threadIdx.x == 0) {
        int all0 = 1;
        for (int i = 1; i < 200; i += 2)
            if (w[i] != 0) { all0 = 0; break; }
        g_is64 = all0;
    }
}

__device__ __forceinline__ int load_idx(const void* ei, long long pos, int is64) {
    if (is64) return (int)((const long long*)ei)[pos];
    return ((const int*)ei)[pos];
}

__global__ void k_zero(int n) {
    int i = blockIdx.x * blockDim.x + threadIdx.x;
    if (i < n) g_deg[i] = 0;
}

// ---------------- input conversions -------------------------------------------
__global__ void k_conv_x(const float* __restrict__ x, int nf4) {
    int i = blockIdx.x * blockDim.x + threadIdx.x;   // over M*128/4
    if (i >= nf4) return;
    float4 v = ((const float4*)x)[i];
    ushort4 hi, lo;
    hi.x = f2bf(v.x); lo.x = f2bf(v.x - bf2f(hi.x));
    hi.y = f2bf(v.y); lo.y = f2bf(v.y - bf2f(hi.y));
    hi.z = f2bf(v.z); lo.z = f2bf(v.z - bf2f(hi.z));
    hi.w = f2bf(v.w); lo.w = f2bf(v.w - bf2f(hi.w));
    ((ushort4*)g_xhi)[i] = hi;
    ((ushort4*)g_xlo)[i] = lo;
}

__global__ void k_conv_w1(const float* __restrict__ W1) {
    int i = blockIdx.x * blockDim.x + threadIdx.x;   // 128*256
    if (i >= 32768) return;
    float w = W1[i];
    unsigned short hi = f2bf(w);
    unsigned short lo = f2bf(w - bf2f(hi));
    g_b1cat[i] = hi; g_b1cat[32768 + i] = hi; g_b1cat[65536 + i] = lo;
}

__global__ void k_conv_w2(const float* __restrict__ W2) {
    int i = blockIdx.x * blockDim.x + threadIdx.x;   // 256*64
    if (i >= 16384) return;
    float w = W2[i];
    unsigned short hi = f2bf(w);
    unsigned short lo = f2bf(w - bf2f(hi));
    g_b2cat[i] = hi; g_b2cat[16384 + i] = hi; g_b2cat[32768 + i] = lo;
}

// ---------------- bf16 split tensor-core GEMM ---------------------------------
// C[M,Nc] = Ahi@B[0:Kp] + Alo@B[Kp:2Kp] + Ahi@B[2Kp:3Kp], fp32 accum.
// Block: 128(M) x 64(N), 256 threads = 8 warps (4x2), warp tile 32x32.
__device__ __forceinline__ void mma16816(float* d, const uint32_t* a, const uint32_t* b) {
    asm volatile(
        "mma.sync.aligned.m16n8k16.row.col.f32.bf16.bf16.f32 "
        "{%0,%1,%2,%3}, {%4,%5,%6,%7}, {%8,%9}, {%0,%1,%2,%3};"
        : "+f"(d[0]), "+f"(d[1]), "+f"(d[2]), "+f"(d[3])
        : "r"(a[0]), "r"(a[1]), "r"(a[2]), "r"(a[3]), "r"(b[0]), "r"(b[1]));
}

__global__ void __launch_bounds__(256) k_gemm_bf16(
    const unsigned short* __restrict__ Ahi, const unsigned short* __restrict__ Alo,
    const unsigned short* __restrict__ Bcat, float* __restrict__ C,
    int M, int Nc, int Kp)
{
    __shared__ unsigned short As[128][40];   // row stride 40 bf16 = 80B (16B mult, conflict-free)
    __shared__ unsigned short Bs[64][40];    // [n][k]
    const int t = threadIdx.x;
    const int wid = t >> 5, lane = t & 31;
    const int gid = lane >> 2, tig = lane & 3;
    const int wm = wid & 3, wn = wid >> 2;
    const int m0 = blockIdx.y * 128, n0 = blockIdx.x * 64;
    const int cpp = Kp >> 5;                 // 32-wide chunks per phase
    const int nch = 3 * cpp;

    float acc[2][4][4];
#pragma unroll
    for (int a = 0; a < 2; a++)
#pragma unroll
        for (int b = 0; b < 4; b++)
#pragma unroll
            for (int c = 0; c < 4; c++) acc[a][b][c] = 0.f;

    const int segA = t & 3, rowA = t >> 2;   // A: 2 rows x 8 cols per thread
    const int kkB = t >> 3, nsegB = t & 7;   // B: 1 k-row x 8 n per thread

    for (int cc = 0; cc < nch; cc++) {
        int phase = cc / cpp;
        int kloc = (cc - phase * cpp) * 32;
        const unsigned short* Ap = (phase == 1) ? Alo : Ahi;
        __syncthreads();
#pragma unroll
        for (int half = 0; half < 2; half++) {
            int r = rowA + half * 64;
            int m = m0 + r;
            uint4 v = make_uint4(0u, 0u, 0u, 0u);
            if (m < M) v = *(const uint4*)(Ap + (size_t)m * Kp + kloc + segA * 8);
            *(uint4*)&As[r][segA * 8] = v;
        }
        {
            uint4 v = *(const uint4*)(Bcat + ((size_t)cc * 32 + kkB) * Nc + n0 + nsegB * 8);
            unsigned short* pv = (unsigned short*)&v;
#pragma unroll
            for (int j = 0; j < 8; j++) Bs[nsegB * 8 + j][kkB] = pv[j];
        }
        __syncthreads();
#pragma unroll
        for (int ks = 0; ks < 32; ks += 16) {
            uint32_t af[2][4];
#pragma unroll
            for (int mt = 0; mt < 2; mt++) {
                int rb = wm * 32 + mt * 16 + gid;
                af[mt][0] = *(const uint32_t*)&As[rb][ks + tig * 2];
                af[mt][1] = *(const uint32_t*)&As[rb + 8][ks + tig * 2];
                af[mt][2] = *(const uint32_t*)&As[rb][ks + tig * 2 + 8];
                af[mt][3] = *(const uint32_t*)&As[rb + 8][ks + tig * 2 + 8];
            }
            uint32_t bfr[4][2];
#pragma unroll
            for (int nt = 0; nt < 4; nt++) {
                int nb = wn * 32 + nt * 8 + gid;
                bfr[nt][0] = *(const uint32_t*)&Bs[nb][ks + tig * 2];
                bfr[nt][1] = *(const uint32_t*)&Bs[nb][ks + tig * 2 + 8];
            }
#pragma unroll
            for (int mt = 0; mt < 2; mt++)
#pragma unroll
                for (int nt = 0; nt < 4; nt++)
                    mma16816(acc[mt][nt], af[mt], bfr[nt]);
        }
    }
#pragma unroll
    for (int mt = 0; mt < 2; mt++) {
#pragma unroll
        for (int nt = 0; nt < 4; nt++) {
            int row = m0 + wm * 32 + mt * 16 + gid;
            int col = n0 + wn * 32 + nt * 8 + tig * 2;
            if (row < M)
                *(float2*)&C[(size_t)row * Nc + col] = make_float2(acc[mt][nt][0], acc[mt][nt][1]);
            if (row + 8 < M)
                *(float2*)&C[(size_t)(row + 8) * Nc + col] = make_float2(acc[mt][nt][2], acc[mt][nt][3]);
        }
    }
}

// ---------------- layer1 attention logits: warp per node ----------------------
__global__ void __launch_bounds__(256) k_att1(const float* __restrict__ att_src,
                                              const float* __restrict__ att_dst, int n)
{
    int warp = (blockIdx.x * blockDim.x + threadIdx.x) >> 5;
    int lane = threadIdx.x & 31;
    if (warp >= n) return;
    float wsrc[8], wdst[8];
#pragma unroll
    for (int h = 0; h < 8; h++) {
        wsrc[h] = att_src[h * 32 + lane];
        wdst[h] = att_dst[h * 32 + lane];
    }
    const float* hp = &g_h1[warp * 256];
    float sa = 0.f, sd = 0.f;
#pragma unroll
    for (int h = 0; h < 8; h++) {
        float v = hp[h * 32 + lane];
        float p1 = v * wsrc[h];
        float p2 = v * wdst[h];
#pragma unroll
        for (int o = 16; o; o >>= 1) {
            p1 += __shfl_xor_sync(0xffffffffu, p1, o);
            p2 += __shfl_xor_sync(0xffffffffu, p2, o);
        }
        if (lane == h) { sa = p1; sd = p2; }
    }
    if (lane < 8) {
        g_asrc1[warp * 8 + lane] = sa;
        g_adst1[warp * 8 + lane] = sd;
    }
}

// ---------------- CSR build ---------------------------------------------------
__global__ void k_count(const void* __restrict__ ei, int e, int n) {
    int i = blockIdx.x * blockDim.x + threadIdx.x;
    if (i >= e + n) return;
    int is64 = g_is64;
    int d = (i < e) ? load_idx(ei, (long long)e + i, is64) : (i - e);
    atomicAdd(&g_deg[d], 1);
}

__global__ void __launch_bounds__(1024) k_scan(int n) {
    const int CH = 49;
    int t = threadIdx.x;
    int base = t * CH;
    int s = 0;
    for (int i = 0; i < CH; i++) { int idx = base + i; if (idx < n) s += g_deg[idx]; }
    int lane = t & 31, wid = t >> 5;
    int v = s;
#pragma unroll
    for (int o = 1; o < 32; o <<= 1) {
        int u = __shfl_up_sync(0xffffffffu, v, o);
        if (lane >= o) v += u;
    }
    __shared__ int ws[32];
    if (lane == 31) ws[wid] = v;
    __syncthreads();
    if (wid == 0) {
        int w = ws[lane];
#pragma unroll
        for (int o = 1; o < 32; o <<= 1) {
            int u = __shfl_up_sync(0xffffffffu, w, o);
            if (lane >= o) w += u;
        }
        ws[lane] = w;
    }
    __syncthreads();
    int excl = v - s + (wid > 0 ? ws[wid - 1] : 0);
    int run = excl;
    for (int i = 0; i < CH; i++) {
        int idx = base + i;
        if (idx < n) { g_rowptr[idx] = run; g_pos[idx] = run; run += g_deg[idx]; }
    }
    if (t == 1023) g_rowptr[n] = excl;
}

__global__ void k_scatter(const void* __restrict__ ei, int e, int n) {
    int i = blockIdx.x * blockDim.x + threadIdx.x;
    if (i >= e + n) return;
    int is64 = g_is64;
    int s, d;
    if (i < e) { s = load_idx(ei, i, is64); d = load_idx(ei, (long long)e + i, is64); }
    else       { s = i - e;                 d = i - e; }
    int p = atomicAdd(&g_pos[d], 1);
    g_ssrc[p] = s;
    g_sdst[p] = d;
}

// ---------------- layer1 softmax numerators (stream, no atomics) --------------
__global__ void k_exp1(int et) {
    int p = blockIdx.x * blockDim.x + threadIdx.x;
    if (p >= et) return;
    int s = g_ssrc[p], d = g_sdst[p];
    const float4* AS = (const float4*)g_asrc1;
    const float4* AD = (const float4*)g_adst1;
    float4 a0 = AS[s * 2], a1 = AS[s * 2 + 1];
    float4 d0 = AD[d * 2], d1 = AD[d * 2 + 1];
    float4 r0, r1;
    float e0;
    e0 = a0.x + d0.x; e0 = e0 > 0.f ? e0 : 0.2f * e0; r0.x = __expf(e0);
    e0 = a0.y + d0.y; e0 = e0 > 0.f ? e0 : 0.2f * e0; r0.y = __expf(e0);
    e0 = a0.z + d0.z; e0 = e0 > 0.f ? e0 : 0.2f * e0; r0.z = __expf(e0);
    e0 = a0.w + d0.w; e0 = e0 > 0.f ? e0 : 0.2f * e0; r0.w = __expf(e0);
    e0 = a1.x + d1.x; e0 = e0 > 0.f ? e0 : 0.2f * e0; r1.x = __expf(e0);
    e0 = a1.y + d1.y; e0 = e0 > 0.f ? e0 : 0.2f * e0; r1.y = __expf(e0);
    e0 = a1.z + d1.z; e0 = e0 > 0.f ? e0 : 0.2f * e0; r1.z = __expf(e0);
    e0 = a1.w + d1.w; e0 = e0 > 0.f ? e0 : 0.2f * e0; r1.w = __expf(e0);
    float4* EX = (float4*)g_expw1;
    EX[p * 2] = r0; EX[p * 2 + 1] = r1;
}

// ---------------- layer1 aggregation + softmax-div + bias + ELU -> bf16 split --
__global__ void __launch_bounds__(256) k_agg1(const float* __restrict__ bias1) {
    int t = threadIdx.x;
    int u = t & 63;
    int d = blockIdx.x * 4 + (t >> 6);
    int h = u >> 3;
    int r0 = g_rowptr[d], r1 = g_rowptr[d + 1];
    const float4* H = (const float4*)g_h1;
    float4 acc = make_float4(0.f, 0.f, 0.f, 0.f);
    float wsum = 0.f;
    int p = r0;
    for (; p + 2 <= r1; p += 2) {
        int s0 = g_ssrc[p],     s1 = g_ssrc[p + 1];
        float w0 = g_expw1[p * 8 + h], w1 = g_expw1[(p + 1) * 8 + h];
        float4 v0 = H[s0 * 64 + u];
        float4 v1 = H[s1 * 64 + u];
        acc.x += w0 * v0.x + w1 * v1.x;
        acc.y += w0 * v0.y + w1 * v1.y;
        acc.z += w0 * v0.z + w1 * v1.z;
        acc.w += w0 * v0.w + w1 * v1.w;
        wsum += w0 + w1;
    }
    if (p < r1) {
        int s0 = g_ssrc[p];
        float w0 = g_expw1[p * 8 + h];
        float4 v0 = H[s0 * 64 + u];
        acc.x += w0 * v0.x; acc.y += w0 * v0.y;
        acc.z += w0 * v0.z; acc.w += w0 * v0.w;
        wsum += w0;
    }
    float sinv = 1.f / (wsum + 1e-16f);
    float4 b = ((const float4*)bias1)[u];
    float4 o;
    o.x = acc.x * sinv + b.x; o.x = o.x > 0.f ? o.x : expm1f(o.x);
    o.y = acc.y * sinv + b.y; o.y = o.y > 0.f ? o.y : expm1f(o.y);
    o.z = acc.z * sinv + b.z; o.z = o.z > 0.f ? o.z : expm1f(o.z);
    o.w = acc.w * sinv + b.w; o.w = o.w > 0.f ? o.w : expm1f(o.w);
    ushort4 hi, lo;
    hi.x = f2bf(o.x); lo.x = f2bf(o.x - bf2f(hi.x));
    hi.y = f2bf(o.y); lo.y = f2bf(o.y - bf2f(hi.y));
    hi.z = f2bf(o.z); lo.z = f2bf(o.z - bf2f(hi.z));
    hi.w = f2bf(o.w); lo.w = f2bf(o.w - bf2f(hi.w));
    ((ushort4*)g_h2hi)[d * 64 + u] = hi;
    ((ushort4*)g_h2lo)[d * 64 + u] = lo;
}

// ---------------- layer2 attention logits (warp per node) ---------------------
__global__ void k_att2(const float* __restrict__ as2,
                       const float* __restrict__ ad2, int n)
{
    int w = (blockIdx.x * blockDim.x + threadIdx.x) >> 5;
    int lane = threadIdx.x & 31;
    if (w >= n) return;
    float v0 = g_h2[w * 64 + lane], v1 = g_h2[w * 64 + 32 + lane];
    float sa = v0 * as2[lane] + v1 * as2[32 + lane];
    float sd = v0 * ad2[lane] + v1 * ad2[32 + lane];
#pragma unroll
    for (int o = 16; o; o >>= 1) {
        sa += __shfl_xor_sync(0xffffffffu, sa, o);
        sd += __shfl_xor_sync(0xffffffffu, sd, o);
    }
    if (lane == 0) { g_asrc2[w] = sa; g_adst2[w] = sd; }
}

__global__ void k_exp2(int et) {
    int p = blockIdx.x * blockDim.x + threadIdx.x;
    if (p >= et) return;
    int s = g_ssrc[p], d = g_sdst[p];
    float ev = g_asrc2[s] + g_adst2[d];
    ev = ev > 0.f ? ev : 0.2f * ev;
    g_expw2[p] = __expf(ev);
}

// ---------------- layer2 aggregation + softmax-div + bias -> output -----------
__global__ void __launch_bounds__(256) k_agg2(const float* __restrict__ bias2,
                                              float* __restrict__ out)
{
    int t = threadIdx.x;
    int u = t & 15;
    int d = blockIdx.x * 16 + (t >> 4);
    int r0 = g_rowptr[d], r1 = g_rowptr[d + 1];
    const float4* H = (const float4*)g_h2;
    float4 acc = make_float4(0.f, 0.f, 0.f, 0.f);
    float wsum = 0.f;
    int p = r0;
    for (; p + 2 <= r1; p += 2) {
        int s0 = g_ssrc[p], s1 = g_ssrc[p + 1];
        float w0 = g_expw2[p], w1 = g_expw2[p + 1];
        float4 v0 = H[s0 * 16 + u];
        float4 v1 = H[s1 * 16 + u];
        acc.x += w0 * v0.x + w1 * v1.x;
        acc.y += w0 * v0.y + w1 * v1.y;
        acc.z += w0 * v0.z + w1 * v1.z;
        acc.w += w0 * v0.w + w1 * v1.w;
        wsum += w0 + w1;
    }
    if (p < r1) {
        int s0 = g_ssrc[p];
        float w0 = g_expw2[p];
        float4 v0 = H[s0 * 16 + u];
        acc.x += w0 * v0.x; acc.y += w0 * v0.y;
        acc.z += w0 * v0.z; acc.w += w0 * v0.w;
        wsum += w0;
    }
    float sinv = 1.f / (wsum + 1e-16f);
    float4 b = ((const float4*)bias2)[u];
    float4 o;
    o.x = acc.x * sinv + b.x;
    o.y = acc.y * sinv + b.y;
    o.z = acc.z * sinv + b.z;
    o.w = acc.w * sinv + b.w;
    ((float4*)out)[d * 16 + u] = o;
}

// ------------------------------------------------------------------------------
extern "C" void kernel_launch(void* const* d_in, const int* in_sizes, int n_in,
                              void* d_out, int out_size)
{
    const float* x   = (const float*)d_in[0];
    const void*  ei  = d_in[1];
    const float* W1  = (const float*)d_in[3];
    const float* as1 = (const float*)d_in[4];
    const float* ad1 = (const float*)d_in[5];
    const float* b1  = (const float*)d_in[6];
    const float* W2  = (const float*)d_in[7];
    const float* as2 = (const float*)d_in[8];
    const float* ad2 = (const float*)d_in[9];
    const float* b2  = (const float*)d_in[10];
    float* out = (float*)d_out;

    const int n  = in_sizes[0] / 128;   // 50000
    const int e  = in_sizes[1] / 2;     // 800000
    const int et = e + n;

    float *h1, *h2;
    unsigned short *xhi, *xlo, *b1cat, *h2hi, *h2lo, *b2cat;
    cudaGetSymbolAddress((void**)&h1,    g_h1);
    cudaGetSymbolAddress((void**)&h2,    g_h2);
    cudaGetSymbolAddress((void**)&xhi,   g_xhi);
    cudaGetSymbolAddress((void**)&xlo,   g_xlo);
    cudaGetSymbolAddress((void**)&b1cat, g_b1cat);
    cudaGetSymbolAddress((void**)&h2hi,  g_h2hi);
    cudaGetSymbolAddress((void**)&h2lo,  g_h2lo);
    cudaGetSymbolAddress((void**)&b2cat, g_b2cat);

    k_detect<<<1, 32>>>((const int*)ei);
    k_zero<<<(n + 255) / 256, 256>>>(n);

    // operand conversions
    int nf4 = n * 32;                   // x float4 count
    k_conv_x<<<(nf4 + 255) / 256, 256>>>(x, nf4);
    k_conv_w1<<<(32768 + 255) / 256, 256>>>(W1);
    k_conv_w2<<<(16384 + 255) / 256, 256>>>(W2);

    // layer1 GEMM (tensor cores): h1 = x @ W1
    k_gemm_bf16<<<dim3(4, (n + 127) / 128), 256>>>(xhi, xlo, b1cat, h1, n, 256, 128);

    // per-node attention logits
    k_att1<<<(n * 32 + 255) / 256, 256>>>(as1, ad1, n);

    // CSR build (shared by both layers)
    k_count<<<(et + 255) / 256, 256>>>(ei, e, n);
    k_scan<<<1, 1024>>>(n);
    k_scatter<<<(et + 255) / 256, 256>>>(ei, e, n);

    // layer1 softmax numerators + aggregation (+bias +elu, emits bf16 hi/lo)
    k_exp1<<<(et + 255) / 256, 256>>>(et);
    k_agg1<<<(n + 3) / 4, 256>>>(b1);

    // layer2 GEMM (tensor cores): h2 = elu_out @ W2
    k_gemm_bf16<<<dim3(1, (n + 127) / 128), 256>>>(h2hi, h2lo, b2cat, h2, n, 64, 256);

    // layer2 logits, softmax, aggregation (+bias) -> output
    k_att2<<<(n * 32 + 255) / 256, 256>>>(as2, ad2, n);
    k_exp2<<<(et + 255) / 256, 256>>>(et);
    k_agg2<<<(n + 15) / 16, 256>>>(b2, out);
}